// round 1
// baseline (speedup 1.0000x reference)
#include <cuda_runtime.h>
#include <cstdint>

#define NN 2048
#define DD 512
#define KPC 8

// Scratch (static __device__ — no allocations allowed)
__device__ float g_x[NN * DD];                 // 4 MB  normalized inputs
__device__ float g_sq[NN];                     // row squared norms (~16)
__device__ float g_dist[(size_t)NN * NN];      // 16 MB distance matrix
__device__ float g_row[NN * 4];                // per-row: cnt, trip_sum, pos_sum, neg_sum

__device__ __forceinline__ float fast_exp2(float x) {
    float y; asm("ex2.approx.f32 %0, %1;" : "=f"(y) : "f"(x)); return y;
}
__device__ __forceinline__ float fast_log2(float x) {
    float y; asm("lg2.approx.f32 %0, %1;" : "=f"(y) : "f"(x)); return y;
}
__device__ __forceinline__ float warp_sum(float v) {
    #pragma unroll
    for (int o = 16; o; o >>= 1) v += __shfl_xor_sync(0xffffffffu, v, o);
    return v;
}

// ---------------------------------------------------------------------------
// 1) Row L2-normalize, scale by ALPHA=4, record sq = ||x||^2
// ---------------------------------------------------------------------------
__global__ __launch_bounds__(128) void normalize_kernel(const float* __restrict__ in) {
    int row = blockIdx.x;
    int t = threadIdx.x;                       // 128 threads, 1 float4 each (D=512)
    float4 v = reinterpret_cast<const float4*>(in + row * DD)[t];
    float ss = v.x * v.x + v.y * v.y + v.z * v.z + v.w * v.w;
    ss = warp_sum(ss);
    __shared__ float ws[4];
    if ((t & 31) == 0) ws[t >> 5] = ss;
    __syncthreads();
    float tot = ws[0] + ws[1] + ws[2] + ws[3];
    float s = 4.0f * rsqrtf(tot);
    float4 o4 = make_float4(v.x * s, v.y * s, v.z * s, v.w * s);
    reinterpret_cast<float4*>(g_x + row * DD)[t] = o4;
    if (t == 0) g_sq[row] = tot * s * s;
}

// ---------------------------------------------------------------------------
// 2) dist[i][j] = sq[i] + sq[j] - 2 * <x_i, x_j>   (128x128x8 tiled SGEMM)
// ---------------------------------------------------------------------------
__global__ __launch_bounds__(256, 2) void dist_kernel() {
    __shared__ float As[8][128];
    __shared__ float Bs[8][128];
    const int bi = blockIdx.y * 128;
    const int bj = blockIdx.x * 128;
    const int tid = threadIdx.x;
    const int lr = tid >> 1;                   // 0..127 load row
    const int lk = (tid & 1) << 2;             // 0 or 4 (k quad)
    const int tx = tid & 15;                   // micro-tile col group
    const int ty = tid >> 4;                   // micro-tile row group

    float acc[8][8];
    #pragma unroll
    for (int r = 0; r < 8; r++)
        #pragma unroll
        for (int c = 0; c < 8; c++) acc[r][c] = 0.0f;

    const float* Aptr = g_x + (bi + lr) * DD + lk;
    const float* Bptr = g_x + (bj + lr) * DD + lk;

    #pragma unroll 1
    for (int k0 = 0; k0 < DD; k0 += 8) {
        float4 a = *reinterpret_cast<const float4*>(Aptr + k0);
        float4 b = *reinterpret_cast<const float4*>(Bptr + k0);
        As[lk + 0][lr] = a.x; As[lk + 1][lr] = a.y;
        As[lk + 2][lr] = a.z; As[lk + 3][lr] = a.w;
        Bs[lk + 0][lr] = b.x; Bs[lk + 1][lr] = b.y;
        Bs[lk + 2][lr] = b.z; Bs[lk + 3][lr] = b.w;
        __syncthreads();
        #pragma unroll
        for (int kk = 0; kk < 8; kk++) {
            float4 a0 = *reinterpret_cast<const float4*>(&As[kk][ty * 8]);
            float4 a1 = *reinterpret_cast<const float4*>(&As[kk][ty * 8 + 4]);
            float4 b0 = *reinterpret_cast<const float4*>(&Bs[kk][tx * 8]);
            float4 b1 = *reinterpret_cast<const float4*>(&Bs[kk][tx * 8 + 4]);
            float ar[8] = {a0.x, a0.y, a0.z, a0.w, a1.x, a1.y, a1.z, a1.w};
            float br[8] = {b0.x, b0.y, b0.z, b0.w, b1.x, b1.y, b1.z, b1.w};
            #pragma unroll
            for (int r = 0; r < 8; r++)
                #pragma unroll
                for (int c = 0; c < 8; c++)
                    acc[r][c] += ar[r] * br[c];
        }
        __syncthreads();
    }

    float sqi[8], sqj[8];
    #pragma unroll
    for (int r = 0; r < 8; r++) sqi[r] = g_sq[bi + ty * 8 + r];
    #pragma unroll
    for (int c = 0; c < 8; c++) sqj[c] = g_sq[bj + tx * 8 + c];

    #pragma unroll
    for (int r = 0; r < 8; r++) {
        int gi = bi + ty * 8 + r;
        #pragma unroll
        for (int cq = 0; cq < 2; cq++) {
            float4 o;
            o.x = sqi[r] + sqj[cq * 4 + 0] - 2.0f * acc[r][cq * 4 + 0];
            o.y = sqi[r] + sqj[cq * 4 + 1] - 2.0f * acc[r][cq * 4 + 1];
            o.z = sqi[r] + sqj[cq * 4 + 2] - 2.0f * acc[r][cq * 4 + 2];
            o.w = sqi[r] + sqj[cq * 4 + 3] - 2.0f * acc[r][cq * 4 + 3];
            *reinterpret_cast<float4*>(&g_dist[(size_t)gi * NN + bj + tx * 8 + cq * 4]) = o;
        }
    }
}

// ---------------------------------------------------------------------------
// 3) Per-row triplet pass.
//    trip(p,n) = ln2 * log2(1 + exp2(p*log2e) * exp2(-n*log2e))
//    valid  <=>  t > e^0.693 - 1 = 0.99970566
// ---------------------------------------------------------------------------
__global__ __launch_bounds__(256) void triplet_kernel() {
    const int i = blockIdx.x;
    const int c = i >> 3;                       // class id (K=8 grouped)
    const float* __restrict__ drow = g_dist + (size_t)i * NN;
    const float L2E = 1.4426950408889634f;
    const float LN2 = 0.6931471805599453f;
    const float CV  = 0.99970566f;              // exp(0.693f) - 1

    __shared__ float Psh[8];
    __shared__ float Pdsh[8];
    if (threadIdx.x < 8) {
        int j = c * KPC + threadIdx.x;
        float pd = drow[j];
        bool self = (j == i);
        Psh[threadIdx.x] = self ? 0.0f : fast_exp2(pd * L2E);
        Pdsh[threadIdx.x] = self ? 0.0f : pd;
    }
    __syncthreads();

    float P[8];
    #pragma unroll
    for (int k = 0; k < 8; k++) P[k] = Psh[k];

    float negsum = 0.0f, trip = 0.0f, cnt = 0.0f;
    for (int j = threadIdx.x; j < NN; j += 256) {
        if ((j >> 3) == c) continue;            // skip same-class (incl. self)
        float nd = drow[j];
        negsum += nd;
        float en = fast_exp2(-nd * L2E);
        #pragma unroll
        for (int k = 0; k < 8; k++) {
            float t = P[k] * en;                // self slot has P=0 -> never valid
            if (t > CV) {
                trip += LN2 * fast_log2(1.0f + t);
                cnt += 1.0f;
            }
        }
    }

    negsum = warp_sum(negsum);
    trip = warp_sum(trip);
    cnt = warp_sum(cnt);
    __shared__ float r0[8], r1[8], r2[8];
    int w = threadIdx.x >> 5, l = threadIdx.x & 31;
    if (l == 0) { r0[w] = negsum; r1[w] = trip; r2[w] = cnt; }
    __syncthreads();
    if (threadIdx.x == 0) {
        float ns = 0, tr = 0, ct = 0;
        #pragma unroll
        for (int ww = 0; ww < 8; ww++) { ns += r0[ww]; tr += r1[ww]; ct += r2[ww]; }
        float ps = 0;
        #pragma unroll
        for (int k = 0; k < 8; k++) ps += Pdsh[k];
        g_row[i * 4 + 0] = ct;
        g_row[i * 4 + 1] = tr;
        g_row[i * 4 + 2] = ps;
        g_row[i * 4 + 3] = ns;
    }
}

// ---------------------------------------------------------------------------
// 4) Finalize: loss, accuracy, pos_d, neg_d (double accumulation: total cnt
//    can exceed 2^24).
// ---------------------------------------------------------------------------
__global__ __launch_bounds__(256) void finalize_kernel(float* __restrict__ out, int out_size) {
    int tid = threadIdx.x;
    double sm = 0, tc = 0, ac = 0, ps = 0, ns = 0;
    for (int i = tid; i < NN; i += 256) {
        float cnt = g_row[i * 4 + 0];
        float tr  = g_row[i * 4 + 1];
        ps += (double)g_row[i * 4 + 2];
        ns += (double)g_row[i * 4 + 3];
        tc += (double)cnt;
        if (cnt > 0.0f) sm += (double)(tr / cnt);
        else            ac += 1.0;
    }
    __shared__ double sh[5][256];
    sh[0][tid] = sm; sh[1][tid] = tc; sh[2][tid] = ac; sh[3][tid] = ps; sh[4][tid] = ns;
    __syncthreads();
    for (int s = 128; s; s >>= 1) {
        if (tid < s) {
            #pragma unroll
            for (int v = 0; v < 5; v++) sh[v][tid] += sh[v][tid + s];
        }
        __syncthreads();
    }
    if (tid == 0) {
        double Sm = sh[0][0], Tc = sh[1][0], Ac = sh[2][0], Ps = sh[3][0], Ns = sh[4][0];
        float loss = (Tc > 0.0) ? (float)(Sm / Tc) : 0.0f;
        if (out_size >= 1) out[0] = loss;
        if (out_size >= 2) out[1] = (float)(Ac / (double)NN);
        if (out_size >= 3) out[2] = (float)(Ps / ((double)NN * (KPC - 1)));
        if (out_size >= 4) out[3] = (float)(Ns / ((double)NN * (NN - KPC)));
    }
    for (int idx = 4 + tid; idx < out_size; idx += 256) out[idx] = 0.0f;
}

// ---------------------------------------------------------------------------
extern "C" void kernel_launch(void* const* d_in, const int* in_sizes, int n_in,
                              void* d_out, int out_size) {
    const float* inputs = (const float*)d_in[0];
    (void)in_sizes; (void)n_in;
    float* out = (float*)d_out;

    normalize_kernel<<<NN, 128>>>(inputs);
    dim3 grid(NN / 128, NN / 128);
    dist_kernel<<<grid, 256>>>();
    triplet_kernel<<<NN, 256>>>();
    finalize_kernel<<<1, 256>>>(out, out_size);
}

// round 2
// speedup vs baseline: 1.0873x; 1.0873x over previous
#include <cuda_runtime.h>
#include <cstdint>

#define NN 2048
#define DD 512
#define KPC 8
#define NT 16                       // 2048/128 row tiles
#define NPAIR_TILES (NT*(NT+1)/2)   // 136 upper-triangular tiles

// Scratch (static __device__ — no allocations allowed)
__device__ float g_x[NN * DD];      // 4 MB  normalized inputs
__device__ float g_sq[NN];          // row squared norms
__device__ float g_pos[NN * 8];     // P_k = exp(p_k) per classmate slot (self = 0)
__device__ float g_row[NN * 4];     // per-row: cnt, trip_sum, pos_sum, neg_sum

__device__ __forceinline__ float fast_exp2(float x) {
    float y; asm("ex2.approx.f32 %0, %1;" : "=f"(y) : "f"(x)); return y;
}
__device__ __forceinline__ float fast_log2(float x) {
    float y; asm("lg2.approx.f32 %0, %1;" : "=f"(y) : "f"(x)); return y;
}
__device__ __forceinline__ float warp_sum(float v) {
    #pragma unroll
    for (int o = 16; o; o >>= 1) v += __shfl_xor_sync(0xffffffffu, v, o);
    return v;
}

// ---------------------------------------------------------------------------
// 1) Row L2-normalize, scale by ALPHA=4, record sq = ||x||^2 (=16)
// ---------------------------------------------------------------------------
__global__ __launch_bounds__(128) void normalize_kernel(const float* __restrict__ in) {
    int row = blockIdx.x;
    int t = threadIdx.x;                       // 128 threads, 1 float4 each (D=512)
    float4 v = reinterpret_cast<const float4*>(in + row * DD)[t];
    float ss = v.x * v.x + v.y * v.y + v.z * v.z + v.w * v.w;
    ss = warp_sum(ss);
    __shared__ float ws[4];
    if ((t & 31) == 0) ws[t >> 5] = ss;
    __syncthreads();
    float tot = ws[0] + ws[1] + ws[2] + ws[3];
    float s = 4.0f * rsqrtf(tot);
    float4 o4 = make_float4(v.x * s, v.y * s, v.z * s, v.w * s);
    reinterpret_cast<float4*>(g_x + row * DD)[t] = o4;
    if (t == 0) g_sq[row] = tot * s * s;
}

// ---------------------------------------------------------------------------
// 2) Per-class positive prep: 8x8 intra-class dists, store P = exp(p) per slot
//    (self slot -> 0, never valid). Also zero-init g_row and store pos_sum.
// ---------------------------------------------------------------------------
__global__ __launch_bounds__(64) void posprep_kernel() {
    const float L2E = 1.4426950408889634f;
    int cls = blockIdx.x;
    int a = threadIdx.x >> 3, b = threadIdx.x & 7;
    int ia = cls * KPC + a, ib = cls * KPC + b;
    const float4* xa = reinterpret_cast<const float4*>(g_x + ia * DD);
    const float4* xb = reinterpret_cast<const float4*>(g_x + ib * DD);
    float dot = 0.0f;
    #pragma unroll 4
    for (int q = 0; q < DD / 4; q++) {
        float4 u = xa[q], v = xb[q];
        dot += u.x * v.x + u.y * v.y + u.z * v.z + u.w * v.w;
    }
    float p = g_sq[ia] + g_sq[ib] - 2.0f * dot;
    bool self = (a == b);
    g_pos[ia * 8 + b] = self ? 0.0f : fast_exp2(p * L2E);
    float ps = self ? 0.0f : p;
    // sum over the 8-lane (b) group
    ps += __shfl_xor_sync(0xffffffffu, ps, 1);
    ps += __shfl_xor_sync(0xffffffffu, ps, 2);
    ps += __shfl_xor_sync(0xffffffffu, ps, 4);
    if (b == 0) {
        g_row[ia * 4 + 0] = 0.0f;   // cnt
        g_row[ia * 4 + 1] = 0.0f;   // trip sum
        g_row[ia * 4 + 2] = ps;     // pos sum
        g_row[ia * 4 + 3] = 0.0f;   // neg sum
    }
}

// ---------------------------------------------------------------------------
// 3) Fused symmetric Gram + triplet epilogue. One 128x128 tile per block,
//    upper-triangular tile set only. Off-diagonal tiles accumulate both
//    orientations (rows of tile-i AND rows of tile-j).
// ---------------------------------------------------------------------------
__global__ __launch_bounds__(256) void fused_kernel() {
    // map linear block -> (ti, tj), ti <= tj
    int bidx = blockIdx.x;
    int ti = 0, rem = bidx;
    #pragma unroll 1
    while (rem >= NT - ti) { rem -= NT - ti; ti++; }
    int tj = ti + rem;
    const int bi = ti * 128, bj = tj * 128;
    const bool offdiag = (ti != tj);

    __shared__ float As[8][128];
    __shared__ float Bs[8][128];
    __shared__ float Pi[128][8];
    __shared__ float Pj[128][8];
    __shared__ float colred[3][128];

    const int tid = threadIdx.x;
    const int lr = tid >> 1;
    const int lk = (tid & 1) << 2;
    const int tx = tid & 15;
    const int ty = tid >> 4;

    float acc[8][8];
    #pragma unroll
    for (int r = 0; r < 8; r++)
        #pragma unroll
        for (int c = 0; c < 8; c++) acc[r][c] = 0.0f;

    const float* Aptr = g_x + (bi + lr) * DD + lk;
    const float* Bptr = g_x + (bj + lr) * DD + lk;

    #pragma unroll 1
    for (int k0 = 0; k0 < DD; k0 += 8) {
        float4 a = *reinterpret_cast<const float4*>(Aptr + k0);
        float4 b = *reinterpret_cast<const float4*>(Bptr + k0);
        As[lk + 0][lr] = a.x; As[lk + 1][lr] = a.y;
        As[lk + 2][lr] = a.z; As[lk + 3][lr] = a.w;
        Bs[lk + 0][lr] = b.x; Bs[lk + 1][lr] = b.y;
        Bs[lk + 2][lr] = b.z; Bs[lk + 3][lr] = b.w;
        __syncthreads();
        #pragma unroll
        for (int kk = 0; kk < 8; kk++) {
            float4 a0 = *reinterpret_cast<const float4*>(&As[kk][ty * 8]);
            float4 a1 = *reinterpret_cast<const float4*>(&As[kk][ty * 8 + 4]);
            float4 b0 = *reinterpret_cast<const float4*>(&Bs[kk][tx * 8]);
            float4 b1 = *reinterpret_cast<const float4*>(&Bs[kk][tx * 8 + 4]);
            float ar[8] = {a0.x, a0.y, a0.z, a0.w, a1.x, a1.y, a1.z, a1.w};
            float br[8] = {b0.x, b0.y, b0.z, b0.w, b1.x, b1.y, b1.z, b1.w};
            #pragma unroll
            for (int r = 0; r < 8; r++)
                #pragma unroll
                for (int c = 0; c < 8; c++)
                    acc[r][c] += ar[r] * br[c];
        }
        __syncthreads();
    }

    // ---- epilogue setup ----
    const float L2E = 1.4426950408889634f;
    const float LN2 = 0.6931471805599453f;
    const float CV  = 0.99970566f;              // exp(0.693f) - 1

    float sqi[8], sqj[8];
    #pragma unroll
    for (int r = 0; r < 8; r++) sqi[r] = g_sq[bi + ty * 8 + r];
    #pragma unroll
    for (int c = 0; c < 8; c++) sqj[c] = g_sq[bj + tx * 8 + c];

    reinterpret_cast<float4*>(&Pi[0][0])[tid] =
        reinterpret_cast<const float4*>(g_pos + bi * 8)[tid];
    reinterpret_cast<float4*>(&Pj[0][0])[tid] =
        reinterpret_cast<const float4*>(g_pos + bj * 8)[tid];
    if (tid < 128) {
        colred[0][tid] = 0.0f; colred[1][tid] = 0.0f; colred[2][tid] = 0.0f;
    }
    __syncthreads();

    // ---- pass 1: row orientation (rows of tile ti) ----
    #pragma unroll
    for (int r = 0; r < 8; r++) {
        const int gi = bi + ty * 8 + r;
        float4 P0 = *reinterpret_cast<const float4*>(&Pi[ty * 8 + r][0]);
        float4 P1 = *reinterpret_cast<const float4*>(&Pi[ty * 8 + r][4]);
        float cnt = 0.0f, trip = 0.0f, neg = 0.0f;
        #pragma unroll
        for (int c = 0; c < 8; c++) {
            const int gj = bj + tx * 8 + c;
            float d = sqi[r] + sqj[c] - 2.0f * acc[r][c];
            bool isneg = offdiag || ((gi >> 3) != (gj >> 3));
            if (isneg) {
                neg += d;
                float en = fast_exp2(-d * L2E);
                float t;
                t = P0.x * en; if (t > CV) { trip += LN2 * fast_log2(1.0f + t); cnt += 1.0f; }
                t = P0.y * en; if (t > CV) { trip += LN2 * fast_log2(1.0f + t); cnt += 1.0f; }
                t = P0.z * en; if (t > CV) { trip += LN2 * fast_log2(1.0f + t); cnt += 1.0f; }
                t = P0.w * en; if (t > CV) { trip += LN2 * fast_log2(1.0f + t); cnt += 1.0f; }
                t = P1.x * en; if (t > CV) { trip += LN2 * fast_log2(1.0f + t); cnt += 1.0f; }
                t = P1.y * en; if (t > CV) { trip += LN2 * fast_log2(1.0f + t); cnt += 1.0f; }
                t = P1.z * en; if (t > CV) { trip += LN2 * fast_log2(1.0f + t); cnt += 1.0f; }
                t = P1.w * en; if (t > CV) { trip += LN2 * fast_log2(1.0f + t); cnt += 1.0f; }
            }
        }
        // reduce over the 16 tx lanes (within warp)
        #pragma unroll
        for (int o = 8; o; o >>= 1) {
            cnt  += __shfl_xor_sync(0xffffffffu, cnt,  o);
            trip += __shfl_xor_sync(0xffffffffu, trip, o);
            neg  += __shfl_xor_sync(0xffffffffu, neg,  o);
        }
        if (tx == 0) {
            atomicAdd(&g_row[gi * 4 + 0], cnt);
            atomicAdd(&g_row[gi * 4 + 1], trip);
            atomicAdd(&g_row[gi * 4 + 3], neg);
        }
    }

    // ---- pass 2: column orientation (rows of tile tj), off-diagonal only ----
    if (offdiag) {
        #pragma unroll
        for (int c = 0; c < 8; c++) {
            float4 Q0 = *reinterpret_cast<const float4*>(&Pj[tx * 8 + c][0]);
            float4 Q1 = *reinterpret_cast<const float4*>(&Pj[tx * 8 + c][4]);
            float cnt = 0.0f, trip = 0.0f, neg = 0.0f;
            #pragma unroll
            for (int r = 0; r < 8; r++) {
                float d = sqi[r] + sqj[c] - 2.0f * acc[r][c];
                neg += d;
                float en = fast_exp2(-d * L2E);
                float t;
                t = Q0.x * en; if (t > CV) { trip += LN2 * fast_log2(1.0f + t); cnt += 1.0f; }
                t = Q0.y * en; if (t > CV) { trip += LN2 * fast_log2(1.0f + t); cnt += 1.0f; }
                t = Q0.z * en; if (t > CV) { trip += LN2 * fast_log2(1.0f + t); cnt += 1.0f; }
                t = Q0.w * en; if (t > CV) { trip += LN2 * fast_log2(1.0f + t); cnt += 1.0f; }
                t = Q1.x * en; if (t > CV) { trip += LN2 * fast_log2(1.0f + t); cnt += 1.0f; }
                t = Q1.y * en; if (t > CV) { trip += LN2 * fast_log2(1.0f + t); cnt += 1.0f; }
                t = Q1.z * en; if (t > CV) { trip += LN2 * fast_log2(1.0f + t); cnt += 1.0f; }
                t = Q1.w * en; if (t > CV) { trip += LN2 * fast_log2(1.0f + t); cnt += 1.0f; }
            }
            atomicAdd(&colred[0][tx * 8 + c], cnt);
            atomicAdd(&colred[1][tx * 8 + c], trip);
            atomicAdd(&colred[2][tx * 8 + c], neg);
        }
        __syncthreads();
        if (tid < 128) {
            const int gj = bj + tid;
            atomicAdd(&g_row[gj * 4 + 0], colred[0][tid]);
            atomicAdd(&g_row[gj * 4 + 1], colred[1][tid]);
            atomicAdd(&g_row[gj * 4 + 3], colred[2][tid]);
        }
    }
}

// ---------------------------------------------------------------------------
// 4) Finalize (double accumulation: total cnt ~15M can approach 2^24)
// ---------------------------------------------------------------------------
__global__ __launch_bounds__(256) void finalize_kernel(float* __restrict__ out, int out_size) {
    int tid = threadIdx.x;
    double sm = 0, tc = 0, ac = 0, ps = 0, ns = 0;
    for (int i = tid; i < NN; i += 256) {
        float cnt = g_row[i * 4 + 0];
        float tr  = g_row[i * 4 + 1];
        ps += (double)g_row[i * 4 + 2];
        ns += (double)g_row[i * 4 + 3];
        tc += (double)cnt;
        if (cnt > 0.0f) sm += (double)(tr / cnt);
        else            ac += 1.0;
    }
    // warp-level double reduction, then cross-warp via smem
    #pragma unroll
    for (int o = 16; o; o >>= 1) {
        sm += __shfl_xor_sync(0xffffffffu, sm, o);
        tc += __shfl_xor_sync(0xffffffffu, tc, o);
        ac += __shfl_xor_sync(0xffffffffu, ac, o);
        ps += __shfl_xor_sync(0xffffffffu, ps, o);
        ns += __shfl_xor_sync(0xffffffffu, ns, o);
    }
    __shared__ double sh[5][8];
    int w = tid >> 5;
    if ((tid & 31) == 0) { sh[0][w] = sm; sh[1][w] = tc; sh[2][w] = ac; sh[3][w] = ps; sh[4][w] = ns; }
    __syncthreads();
    if (tid == 0) {
        double Sm = 0, Tc = 0, Ac = 0, Ps = 0, Ns = 0;
        #pragma unroll
        for (int ww = 0; ww < 8; ww++) {
            Sm += sh[0][ww]; Tc += sh[1][ww]; Ac += sh[2][ww]; Ps += sh[3][ww]; Ns += sh[4][ww];
        }
        float loss = (Tc > 0.0) ? (float)(Sm / Tc) : 0.0f;
        if (out_size >= 1) out[0] = loss;
        if (out_size >= 2) out[1] = (float)(Ac / (double)NN);
        if (out_size >= 3) out[2] = (float)(Ps / ((double)NN * (KPC - 1)));
        if (out_size >= 4) out[3] = (float)(Ns / ((double)NN * (NN - KPC)));
    }
    for (int idx = 4 + tid; idx < out_size; idx += 256) out[idx] = 0.0f;
}

// ---------------------------------------------------------------------------
extern "C" void kernel_launch(void* const* d_in, const int* in_sizes, int n_in,
                              void* d_out, int out_size) {
    const float* inputs = (const float*)d_in[0];
    (void)in_sizes; (void)n_in;
    float* out = (float*)d_out;

    normalize_kernel<<<NN, 128>>>(inputs);
    posprep_kernel<<<NN / KPC, 64>>>();
    fused_kernel<<<NPAIR_TILES, 256>>>();
    finalize_kernel<<<1, 256>>>(out, out_size);
}

// round 4
// speedup vs baseline: 1.3360x; 1.2287x over previous
#include <cuda_runtime.h>
#include <cuda_bf16.h>
#include <cstdint>

#define NN 2048
#define DD 512
#define KPC 8
#define TM 128
#define TN 256
#define KS 64
#define NSLAB (DD / KS)

// ---------------- scratch (no allocations allowed) ----------------
__device__ float g_x[NN * DD];               // fp32 normalized (for posprep)
__device__ __nv_bfloat16 g_xh[NN * DD];      // bf16 hi
__device__ __nv_bfloat16 g_xl[NN * DD];      // bf16 lo residual
__device__ float g_sq[NN];
__device__ float g_pos[NN * 8];              // P_k = exp(pos dist), self slot = 0
__device__ float g_row[NN * 4];              // cnt, trip_sum, pos_sum, neg_sum
__device__ int g_done;

// ---------------- helpers ----------------
__device__ __forceinline__ uint32_t smem_to_u32(const void* p) {
    uint32_t a;
    asm("{ .reg .u64 t; cvta.to.shared.u64 t, %1; cvt.u32.u64 %0, t; }" : "=r"(a) : "l"(p));
    return a;
}
__device__ __forceinline__ float fast_exp2(float x) { float y; asm("ex2.approx.f32 %0, %1;" : "=f"(y) : "f"(x)); return y; }
__device__ __forceinline__ float fast_log2(float x) { float y; asm("lg2.approx.f32 %0, %1;" : "=f"(y) : "f"(x)); return y; }
__device__ __forceinline__ float warp_sum(float v) {
    #pragma unroll
    for (int o = 16; o; o >>= 1) v += __shfl_xor_sync(0xffffffffu, v, o);
    return v;
}

#define CPA(dst, src) \
    asm volatile("cp.async.cg.shared.global [%0], [%1], 16;" :: "r"(dst), "l"(src))
#define CPA_COMMIT() asm volatile("cp.async.commit_group;" ::: "memory")

__device__ __forceinline__ void ldm_x4(uint32_t* r, uint32_t addr) {
    asm volatile("ldmatrix.sync.aligned.m8n8.x4.shared.b16 {%0,%1,%2,%3}, [%4];"
                 : "=r"(r[0]), "=r"(r[1]), "=r"(r[2]), "=r"(r[3]) : "r"(addr));
}
__device__ __forceinline__ void mma_bf16(float* c, const uint32_t* a, uint32_t b0, uint32_t b1) {
    asm volatile(
        "mma.sync.aligned.m16n8k16.row.col.f32.bf16.bf16.f32 "
        "{%0,%1,%2,%3}, {%4,%5,%6,%7}, {%8,%9}, {%0,%1,%2,%3};"
        : "+f"(c[0]), "+f"(c[1]), "+f"(c[2]), "+f"(c[3])
        : "r"(a[0]), "r"(a[1]), "r"(a[2]), "r"(a[3]), "r"(b0), "r"(b1));
}

// ---------------------------------------------------------------------------
// 1) normalize: x = 4*in/||in||, write fp32 + bf16 hi/lo split + sq; reset g_done
// ---------------------------------------------------------------------------
__global__ __launch_bounds__(128) void normalize_kernel(const float* __restrict__ in) {
    int row = blockIdx.x;
    int t = threadIdx.x;
    if (row == 0 && t == 0) g_done = 0;
    float4 v = reinterpret_cast<const float4*>(in + row * DD)[t];
    float ss = v.x * v.x + v.y * v.y + v.z * v.z + v.w * v.w;
    ss = warp_sum(ss);
    __shared__ float ws[4];
    if ((t & 31) == 0) ws[t >> 5] = ss;
    __syncthreads();
    float tot = ws[0] + ws[1] + ws[2] + ws[3];
    float s = 4.0f * rsqrtf(tot);
    float4 o4 = make_float4(v.x * s, v.y * s, v.z * s, v.w * s);
    reinterpret_cast<float4*>(g_x + row * DD)[t] = o4;

    __nv_bfloat16 hx = __float2bfloat16_rn(o4.x), hy = __float2bfloat16_rn(o4.y);
    __nv_bfloat16 hz = __float2bfloat16_rn(o4.z), hw = __float2bfloat16_rn(o4.w);
    __nv_bfloat162* ph = reinterpret_cast<__nv_bfloat162*>(g_xh + row * DD + t * 4);
    ph[0] = __nv_bfloat162(hx, hy);
    ph[1] = __nv_bfloat162(hz, hw);
    __nv_bfloat162* pl = reinterpret_cast<__nv_bfloat162*>(g_xl + row * DD + t * 4);
    pl[0] = __nv_bfloat162(__float2bfloat16_rn(o4.x - __bfloat162float(hx)),
                           __float2bfloat16_rn(o4.y - __bfloat162float(hy)));
    pl[1] = __nv_bfloat162(__float2bfloat16_rn(o4.z - __bfloat162float(hz)),
                           __float2bfloat16_rn(o4.w - __bfloat162float(hw)));
    if (t == 0) g_sq[row] = tot * s * s;
}

// ---------------------------------------------------------------------------
// 2) posprep: per-class 8x8 fp32 dists -> P=exp(p) (self=0), init g_row
// ---------------------------------------------------------------------------
__global__ __launch_bounds__(64) void posprep_kernel() {
    const float L2E = 1.4426950408889634f;
    int cls = blockIdx.x;
    int a = threadIdx.x >> 3, b = threadIdx.x & 7;
    int ia = cls * KPC + a, ib = cls * KPC + b;
    const float4* xa = reinterpret_cast<const float4*>(g_x + ia * DD);
    const float4* xb = reinterpret_cast<const float4*>(g_x + ib * DD);
    float dot = 0.0f;
    #pragma unroll 4
    for (int q = 0; q < DD / 4; q++) {
        float4 u = xa[q], v = xb[q];
        dot += u.x * v.x + u.y * v.y + u.z * v.z + u.w * v.w;
    }
    float p = g_sq[ia] + g_sq[ib] - 2.0f * dot;
    bool self = (a == b);
    g_pos[ia * 8 + b] = self ? 0.0f : fast_exp2(p * L2E);
    float ps = self ? 0.0f : p;
    ps += __shfl_xor_sync(0xffffffffu, ps, 1);
    ps += __shfl_xor_sync(0xffffffffu, ps, 2);
    ps += __shfl_xor_sync(0xffffffffu, ps, 4);
    if (b == 0) {
        g_row[ia * 4 + 0] = 0.0f;
        g_row[ia * 4 + 1] = 0.0f;
        g_row[ia * 4 + 2] = ps;
        g_row[ia * 4 + 3] = 0.0f;
    }
}

// ---------------------------------------------------------------------------
// 3) fused HMMA Gram + triplet epilogue + last-block finalize
// ---------------------------------------------------------------------------
#define SM_SQI 0
#define SM_SQJ 512
#define SM_PI  1536
#define SM_BUF 6144
#define AH_OFF 0
#define AL_OFF 16384
#define BH_OFF 32768
#define BL_OFF 65536
#define BUFSZ  98304
#define SMEM_TOTAL (SM_BUF + 2 * BUFSZ)

__device__ __forceinline__ void load_slab_async(uint32_t smb, int buf, int s,
                                                int bi, int bj, int tid) {
    const int k0 = s * KS;
    const uint32_t bufb = smb + SM_BUF + buf * BUFSZ;
    // A hi/lo: 128 rows x 8 chunks of 16B; 2 threads per row
    {
        int row = tid >> 1;
        int cb = (tid & 1) * 4;
        const char* sh = reinterpret_cast<const char*>(g_xh + (bi + row) * DD + k0);
        const char* sl = reinterpret_cast<const char*>(g_xl + (bi + row) * DD + k0);
        uint32_t dA = bufb + row * 128;
        #pragma unroll
        for (int c = 0; c < 4; c++) {
            int ch = cb + c;
            uint32_t d = dA + (((ch ^ (row & 7))) << 4);
            CPA(d + AH_OFF, sh + ch * 16);
            CPA(d + AL_OFF, sl + ch * 16);
        }
    }
    // B hi/lo: 256 rows x 8 chunks; 1 thread per row
    {
        int row = tid;
        const char* sh = reinterpret_cast<const char*>(g_xh + (bj + row) * DD + k0);
        const char* sl = reinterpret_cast<const char*>(g_xl + (bj + row) * DD + k0);
        uint32_t dB = bufb + row * 128;
        #pragma unroll
        for (int ch = 0; ch < 8; ch++) {
            uint32_t d = dB + (((ch ^ (row & 7))) << 4);
            CPA(d + BH_OFF, sh + ch * 16);
            CPA(d + BL_OFF, sl + ch * 16);
        }
    }
}

__global__ __launch_bounds__(256, 1) void fused_kernel(float* __restrict__ out, int out_size) {
    extern __shared__ char smem[];
    const int tid = threadIdx.x;
    const int wid = tid >> 5;
    const int lane = tid & 31;
    const int bi = blockIdx.y * TM;
    const int bj = blockIdx.x * TN;
    const int mloc = (wid >> 2) * 64;
    const int nloc = (wid & 3) * 64;
    const uint32_t smb = smem_to_u32(smem);
    float* sSqi = reinterpret_cast<float*>(smem + SM_SQI);
    float* sSqj = reinterpret_cast<float*>(smem + SM_SQJ);
    float* sPi  = reinterpret_cast<float*>(smem + SM_PI);

    load_slab_async(smb, 0, 0, bi, bj, tid);
    CPA_COMMIT();

    if (tid < 128) sSqi[tid] = g_sq[bi + tid];
    sSqj[tid] = g_sq[bj + tid];
    reinterpret_cast<float4*>(sPi)[tid] = reinterpret_cast<const float4*>(g_pos + bi * 8)[tid];

    float acc[4][8][4];
    #pragma unroll
    for (int mi = 0; mi < 4; mi++)
        #pragma unroll
        for (int ni = 0; ni < 8; ni++)
            #pragma unroll
            for (int r = 0; r < 4; r++) acc[mi][ni][r] = 0.0f;

    // per-lane ldmatrix addressing components
    const int rA = (lane & 7) + (((lane >> 3) & 1) << 3);   // row within 16
    const int cSel = lane >> 4;                              // 0/1 -> k chunk
    const int x7 = lane & 7;

    #pragma unroll 1
    for (int s = 0; s < NSLAB; s++) {
        const int b = s & 1;
        if (s + 1 < NSLAB) { load_slab_async(smb, 1 - b, s + 1, bi, bj, tid); CPA_COMMIT(); }
        if (s + 1 < NSLAB) asm volatile("cp.async.wait_group 1;" ::: "memory");
        else               asm volatile("cp.async.wait_group 0;" ::: "memory");
        __syncthreads();

        const uint32_t base = smb + SM_BUF + b * BUFSZ;
        #pragma unroll
        for (int term = 0; term < 3; term++) {
            const uint32_t aOff = (term == 2) ? AL_OFF : AH_OFF;
            const uint32_t bOff = (term == 1) ? BL_OFF : BH_OFF;
            #pragma unroll
            for (int ks = 0; ks < 4; ks++) {
                uint32_t af[4][4];
                #pragma unroll
                for (int mi = 0; mi < 4; mi++) {
                    int row = mloc + mi * 16 + rA;
                    uint32_t ad = base + aOff + row * 128 + ((((2 * ks + cSel) ^ x7)) << 4);
                    ldm_x4(af[mi], ad);
                }
                uint32_t bfr[4][4];
                #pragma unroll
                for (int nt = 0; nt < 4; nt++) {
                    int row = nloc + nt * 16 + rA;
                    uint32_t bd = base + bOff + row * 128 + ((((2 * ks + cSel) ^ x7)) << 4);
                    ldm_x4(bfr[nt], bd);
                }
                #pragma unroll
                for (int mi = 0; mi < 4; mi++)
                    #pragma unroll
                    for (int nt = 0; nt < 4; nt++) {
                        mma_bf16(acc[mi][2 * nt],     af[mi], bfr[nt][0], bfr[nt][2]);
                        mma_bf16(acc[mi][2 * nt + 1], af[mi], bfr[nt][1], bfr[nt][3]);
                    }
            }
        }
        __syncthreads();
    }

    // ---- triplet epilogue on register accumulators ----
    const float L2E = 1.4426950408889634f;
    const float LN2 = 0.6931471805599453f;
    const float TH  = 1.99970566f;            // 1 + (exp(0.693f)-1)

    #pragma unroll
    for (int mi = 0; mi < 4; mi++) {
        #pragma unroll
        for (int h = 0; h < 2; h++) {
            const int rl = mloc + mi * 16 + h * 8 + (lane >> 2);
            const int gi = bi + rl;
            const float sqi = sSqi[rl];
            const float4 p0 = *reinterpret_cast<const float4*>(sPi + rl * 8);
            const float4 p1 = *reinterpret_cast<const float4*>(sPi + rl * 8 + 4);
            float cnt = 0.0f, trip = 0.0f, neg = 0.0f;
            #pragma unroll
            for (int ni = 0; ni < 8; ni++) {
                #pragma unroll
                for (int rr = 0; rr < 2; rr++) {
                    const int cl = nloc + ni * 8 + (lane & 3) * 2 + rr;
                    const float d = sqi + sSqj[cl] - 2.0f * acc[mi][ni][h * 2 + rr];
                    const int gj = bj + cl;
                    if ((gi >> 3) != (gj >> 3)) {
                        neg += d;
                        float en = fast_exp2(-d * L2E);
                        float f0 = fmaf(p0.x, en, 1.0f);
                        float f1 = fmaf(p0.y, en, 1.0f);
                        float f2 = fmaf(p0.z, en, 1.0f);
                        float f3 = fmaf(p0.w, en, 1.0f);
                        float f4 = fmaf(p1.x, en, 1.0f);
                        float f5 = fmaf(p1.y, en, 1.0f);
                        float f6 = fmaf(p1.z, en, 1.0f);
                        float f7 = fmaf(p1.w, en, 1.0f);
                        cnt += (f0 > TH) ? 1.0f : 0.0f;
                        cnt += (f1 > TH) ? 1.0f : 0.0f;
                        cnt += (f2 > TH) ? 1.0f : 0.0f;
                        cnt += (f3 > TH) ? 1.0f : 0.0f;
                        cnt += (f4 > TH) ? 1.0f : 0.0f;
                        cnt += (f5 > TH) ? 1.0f : 0.0f;
                        cnt += (f6 > TH) ? 1.0f : 0.0f;
                        cnt += (f7 > TH) ? 1.0f : 0.0f;
                        float pa = ((f0 > TH) ? f0 : 1.0f);
                        pa *= ((f1 > TH) ? f1 : 1.0f);
                        pa *= ((f2 > TH) ? f2 : 1.0f);
                        pa *= ((f3 > TH) ? f3 : 1.0f);
                        float pb = ((f4 > TH) ? f4 : 1.0f);
                        pb *= ((f5 > TH) ? f5 : 1.0f);
                        pb *= ((f6 > TH) ? f6 : 1.0f);
                        pb *= ((f7 > TH) ? f7 : 1.0f);
                        trip += LN2 * (fast_log2(pa) + fast_log2(pb));
                    }
                }
            }
            cnt  += __shfl_xor_sync(0xffffffffu, cnt, 1);
            cnt  += __shfl_xor_sync(0xffffffffu, cnt, 2);
            trip += __shfl_xor_sync(0xffffffffu, trip, 1);
            trip += __shfl_xor_sync(0xffffffffu, trip, 2);
            neg  += __shfl_xor_sync(0xffffffffu, neg, 1);
            neg  += __shfl_xor_sync(0xffffffffu, neg, 2);
            if ((lane & 3) == 0) {
                atomicAdd(&g_row[gi * 4 + 0], cnt);
                atomicAdd(&g_row[gi * 4 + 1], trip);
                atomicAdd(&g_row[gi * 4 + 3], neg);
            }
        }
    }

    // ---- last-block finalize ----
    __syncthreads();
    __shared__ int slast;
    if (tid == 0) {
        __threadfence();
        int o = atomicAdd(&g_done, 1);
        slast = (o == (int)(gridDim.x * gridDim.y) - 1);
    }
    __syncthreads();
    if (!slast) return;
    __threadfence();

    double sm = 0, tc = 0, acd = 0, psd = 0, nsd = 0;
    for (int i = tid; i < NN; i += 256) {
        float4 r = *reinterpret_cast<const float4*>(g_row + i * 4);
        tc += (double)r.x; psd += (double)r.z; nsd += (double)r.w;
        if (r.x > 0.0f) sm += (double)(r.y / r.x);
        else            acd += 1.0;
    }
    #pragma unroll
    for (int o = 16; o; o >>= 1) {
        sm  += __shfl_xor_sync(0xffffffffu, sm, o);
        tc  += __shfl_xor_sync(0xffffffffu, tc, o);
        acd += __shfl_xor_sync(0xffffffffu, acd, o);
        psd += __shfl_xor_sync(0xffffffffu, psd, o);
        nsd += __shfl_xor_sync(0xffffffffu, nsd, o);
    }
    __shared__ double sh[5][8];
    int w = tid >> 5;
    if ((tid & 31) == 0) { sh[0][w] = sm; sh[1][w] = tc; sh[2][w] = acd; sh[3][w] = psd; sh[4][w] = nsd; }
    __syncthreads();
    if (tid == 0) {
        double Sm = 0, Tc = 0, Ac = 0, Ps = 0, Ns = 0;
        #pragma unroll
        for (int ww = 0; ww < 8; ww++) {
            Sm += sh[0][ww]; Tc += sh[1][ww]; Ac += sh[2][ww]; Ps += sh[3][ww]; Ns += sh[4][ww];
        }
        float loss = (Tc > 0.0) ? (float)(Sm / Tc) : 0.0f;
        if (out_size >= 1) out[0] = loss;
        if (out_size >= 2) out[1] = (float)(Ac / (double)NN);
        if (out_size >= 3) out[2] = (float)(Ps / ((double)NN * (KPC - 1)));
        if (out_size >= 4) out[3] = (float)(Ns / ((double)NN * (NN - KPC)));
    }
    for (int idx = 4 + tid; idx < out_size; idx += 256) out[idx] = 0.0f;
}

// ---------------------------------------------------------------------------
extern "C" void kernel_launch(void* const* d_in, const int* in_sizes, int n_in,
                              void* d_out, int out_size) {
    const float* inputs = (const float*)d_in[0];
    (void)in_sizes; (void)n_in;
    float* out = (float*)d_out;

    cudaFuncSetAttribute(fused_kernel, cudaFuncAttributeMaxDynamicSharedMemorySize, SMEM_TOTAL);

    normalize_kernel<<<NN, 128>>>(inputs);
    posprep_kernel<<<NN / KPC, 64>>>();
    fused_kernel<<<dim3(NN / TN, NN / TM), 256, SMEM_TOTAL>>>(out, out_size);
}

// round 5
// speedup vs baseline: 2.0222x; 1.5136x over previous
#include <cuda_runtime.h>
#include <cuda_fp16.h>
#include <cstdint>

#define NN 2048
#define DD 512
#define KPC 8
#define TM 128
#define TN 256
#define KS 64
#define NSLAB (DD / KS)

// ---------------- scratch (no allocations allowed) ----------------
__device__ float g_x[NN * DD];               // fp32 normalized (for posprep)
__device__ __half g_xf[NN * DD];             // fp16 normalized (MMA operand)
__device__ float g_sq[NN];
__device__ float g_pos[NN * 8];              // P_k = exp(pos dist), self slot = 0
__device__ float g_row[NN * 4];              // cnt, trip_sum, pos_sum, neg_sum
__device__ int g_done;

// ---------------- helpers ----------------
__device__ __forceinline__ uint32_t smem_to_u32(const void* p) {
    uint32_t a;
    asm("{ .reg .u64 t; cvta.to.shared.u64 t, %1; cvt.u32.u64 %0, t; }" : "=r"(a) : "l"(p));
    return a;
}
__device__ __forceinline__ float fast_exp2(float x) { float y; asm("ex2.approx.f32 %0, %1;" : "=f"(y) : "f"(x)); return y; }
__device__ __forceinline__ float fast_log2(float x) { float y; asm("lg2.approx.f32 %0, %1;" : "=f"(y) : "f"(x)); return y; }
__device__ __forceinline__ float warp_sum(float v) {
    #pragma unroll
    for (int o = 16; o; o >>= 1) v += __shfl_xor_sync(0xffffffffu, v, o);
    return v;
}

#define CPA(dst, src) \
    asm volatile("cp.async.cg.shared.global [%0], [%1], 16;" :: "r"(dst), "l"(src))
#define CPA_COMMIT() asm volatile("cp.async.commit_group;" ::: "memory")

__device__ __forceinline__ void ldm_x4(uint32_t* r, uint32_t addr) {
    asm volatile("ldmatrix.sync.aligned.m8n8.x4.shared.b16 {%0,%1,%2,%3}, [%4];"
                 : "=r"(r[0]), "=r"(r[1]), "=r"(r[2]), "=r"(r[3]) : "r"(addr));
}
__device__ __forceinline__ void mma_fp16(float* c, const uint32_t* a, uint32_t b0, uint32_t b1) {
    asm volatile(
        "mma.sync.aligned.m16n8k16.row.col.f32.f16.f16.f32 "
        "{%0,%1,%2,%3}, {%4,%5,%6,%7}, {%8,%9}, {%0,%1,%2,%3};"
        : "+f"(c[0]), "+f"(c[1]), "+f"(c[2]), "+f"(c[3])
        : "r"(a[0]), "r"(a[1]), "r"(a[2]), "r"(a[3]), "r"(b0), "r"(b1));
}

// ---------------------------------------------------------------------------
// 1) normalize: x = 4*in/||in||, write fp32 + fp16 + sq; reset g_done
// ---------------------------------------------------------------------------
__global__ __launch_bounds__(128) void normalize_kernel(const float* __restrict__ in) {
    int row = blockIdx.x;
    int t = threadIdx.x;
    if (row == 0 && t == 0) g_done = 0;
    float4 v = reinterpret_cast<const float4*>(in + row * DD)[t];
    float ss = v.x * v.x + v.y * v.y + v.z * v.z + v.w * v.w;
    ss = warp_sum(ss);
    __shared__ float ws[4];
    if ((t & 31) == 0) ws[t >> 5] = ss;
    __syncthreads();
    float tot = ws[0] + ws[1] + ws[2] + ws[3];
    float s = 4.0f * rsqrtf(tot);
    float4 o4 = make_float4(v.x * s, v.y * s, v.z * s, v.w * s);
    reinterpret_cast<float4*>(g_x + row * DD)[t] = o4;

    __half2* pf = reinterpret_cast<__half2*>(g_xf + row * DD + t * 4);
    pf[0] = __half2(__float2half_rn(o4.x), __float2half_rn(o4.y));
    pf[1] = __half2(__float2half_rn(o4.z), __float2half_rn(o4.w));
    if (t == 0) g_sq[row] = tot * s * s;
}

// ---------------------------------------------------------------------------
// 2) posprep: per-class 8x8 fp32 dists -> P=exp(p) (self=0), init g_row
// ---------------------------------------------------------------------------
__global__ __launch_bounds__(64) void posprep_kernel() {
    const float L2E = 1.4426950408889634f;
    int cls = blockIdx.x;
    int a = threadIdx.x >> 3, b = threadIdx.x & 7;
    int ia = cls * KPC + a, ib = cls * KPC + b;
    const float4* xa = reinterpret_cast<const float4*>(g_x + ia * DD);
    const float4* xb = reinterpret_cast<const float4*>(g_x + ib * DD);
    float dot = 0.0f;
    #pragma unroll 4
    for (int q = 0; q < DD / 4; q++) {
        float4 u = xa[q], v = xb[q];
        dot += u.x * v.x + u.y * v.y + u.z * v.z + u.w * v.w;
    }
    float p = g_sq[ia] + g_sq[ib] - 2.0f * dot;
    bool self = (a == b);
    g_pos[ia * 8 + b] = self ? 0.0f : fast_exp2(p * L2E);
    float ps = self ? 0.0f : p;
    ps += __shfl_xor_sync(0xffffffffu, ps, 1);
    ps += __shfl_xor_sync(0xffffffffu, ps, 2);
    ps += __shfl_xor_sync(0xffffffffu, ps, 4);
    if (b == 0) {
        g_row[ia * 4 + 0] = 0.0f;
        g_row[ia * 4 + 1] = 0.0f;
        g_row[ia * 4 + 2] = ps;
        g_row[ia * 4 + 3] = 0.0f;
    }
}

// ---------------------------------------------------------------------------
// 3) fused HMMA(fp16) Gram + triplet epilogue + last-block finalize
// ---------------------------------------------------------------------------
#define SM_SQI 0
#define SM_SQJ 512
#define SM_PI  1536
#define SM_BUF 6144
#define A_OFF 0
#define B_OFF 16384
#define BUFSZ 49152
#define SMEM_TOTAL (SM_BUF + 2 * BUFSZ)

__device__ __forceinline__ void load_slab_async(uint32_t smb, int buf, int s,
                                                int bi, int bj, int tid) {
    const int k0 = s * KS;
    const uint32_t bufb = smb + SM_BUF + buf * BUFSZ;
    // A: 128 rows x 8 chunks of 16B; 2 threads per row
    {
        int row = tid >> 1;
        int cb = (tid & 1) * 4;
        const char* sp = reinterpret_cast<const char*>(g_xf + (bi + row) * DD + k0);
        uint32_t dA = bufb + A_OFF + row * 128;
        #pragma unroll
        for (int c = 0; c < 4; c++) {
            int ch = cb + c;
            CPA(dA + (((ch ^ (row & 7))) << 4), sp + ch * 16);
        }
    }
    // B: 256 rows x 8 chunks; 1 thread per row
    {
        int row = tid;
        const char* sp = reinterpret_cast<const char*>(g_xf + (bj + row) * DD + k0);
        uint32_t dB = bufb + B_OFF + row * 128;
        #pragma unroll
        for (int ch = 0; ch < 8; ch++) {
            CPA(dB + (((ch ^ (row & 7))) << 4), sp + ch * 16);
        }
    }
}

__global__ __launch_bounds__(256, 1) void fused_kernel(float* __restrict__ out, int out_size) {
    extern __shared__ char smem[];
    const int tid = threadIdx.x;
    const int wid = tid >> 5;
    const int lane = tid & 31;
    const int bi = blockIdx.y * TM;
    const int bj = blockIdx.x * TN;
    const int mloc = (wid >> 2) * 64;
    const int nloc = (wid & 3) * 64;
    const uint32_t smb = smem_to_u32(smem);
    float* sSqi = reinterpret_cast<float*>(smem + SM_SQI);
    float* sSqj = reinterpret_cast<float*>(smem + SM_SQJ);
    float* sPi  = reinterpret_cast<float*>(smem + SM_PI);

    load_slab_async(smb, 0, 0, bi, bj, tid);
    CPA_COMMIT();

    if (tid < 128) sSqi[tid] = g_sq[bi + tid];
    sSqj[tid] = g_sq[bj + tid];
    reinterpret_cast<float4*>(sPi)[tid] = reinterpret_cast<const float4*>(g_pos + bi * 8)[tid];

    float acc[4][8][4];
    #pragma unroll
    for (int mi = 0; mi < 4; mi++)
        #pragma unroll
        for (int ni = 0; ni < 8; ni++)
            #pragma unroll
            for (int r = 0; r < 4; r++) acc[mi][ni][r] = 0.0f;

    const int rA = (lane & 7) + (((lane >> 3) & 1) << 3);
    const int cSel = lane >> 4;
    const int x7 = lane & 7;

    #pragma unroll 1
    for (int s = 0; s < NSLAB; s++) {
        const int b = s & 1;
        if (s + 1 < NSLAB) { load_slab_async(smb, 1 - b, s + 1, bi, bj, tid); CPA_COMMIT(); }
        if (s + 1 < NSLAB) asm volatile("cp.async.wait_group 1;" ::: "memory");
        else               asm volatile("cp.async.wait_group 0;" ::: "memory");
        __syncthreads();

        const uint32_t base = smb + SM_BUF + b * BUFSZ;
        #pragma unroll
        for (int ks = 0; ks < 4; ks++) {
            uint32_t af[4][4];
            #pragma unroll
            for (int mi = 0; mi < 4; mi++) {
                int row = mloc + mi * 16 + rA;
                uint32_t ad = base + A_OFF + row * 128 + ((((2 * ks + cSel) ^ x7)) << 4);
                ldm_x4(af[mi], ad);
            }
            uint32_t bfr[4][4];
            #pragma unroll
            for (int nt = 0; nt < 4; nt++) {
                int row = nloc + nt * 16 + rA;
                uint32_t bd = base + B_OFF + row * 128 + ((((2 * ks + cSel) ^ x7)) << 4);
                ldm_x4(bfr[nt], bd);
            }
            #pragma unroll
            for (int mi = 0; mi < 4; mi++)
                #pragma unroll
                for (int nt = 0; nt < 4; nt++) {
                    mma_fp16(acc[mi][2 * nt],     af[mi], bfr[nt][0], bfr[nt][2]);
                    mma_fp16(acc[mi][2 * nt + 1], af[mi], bfr[nt][1], bfr[nt][3]);
                }
        }
        __syncthreads();
    }

    // ---- triplet epilogue on register accumulators ----
    const float L2E = 1.4426950408889634f;
    const float LN2 = 0.6931471805599453f;
    const float TH  = 1.99970566f;            // 1 + (exp(0.693f)-1)

    #pragma unroll
    for (int mi = 0; mi < 4; mi++) {
        #pragma unroll
        for (int h = 0; h < 2; h++) {
            const int rl = mloc + mi * 16 + h * 8 + (lane >> 2);
            const int gi = bi + rl;
            const float sqi = sSqi[rl];
            const float4 p0 = *reinterpret_cast<const float4*>(sPi + rl * 8);
            const float4 p1 = *reinterpret_cast<const float4*>(sPi + rl * 8 + 4);
            float cnt = 0.0f, trip = 0.0f, neg = 0.0f;
            #pragma unroll
            for (int ni = 0; ni < 8; ni++) {
                #pragma unroll
                for (int rr = 0; rr < 2; rr++) {
                    const int cl = nloc + ni * 8 + (lane & 3) * 2 + rr;
                    const float d = sqi + sSqj[cl] - 2.0f * acc[mi][ni][h * 2 + rr];
                    const int gj = bj + cl;
                    if ((gi >> 3) != (gj >> 3)) {
                        neg += d;
                        float en = fast_exp2(-d * L2E);
                        float f0 = fmaf(p0.x, en, 1.0f);
                        float f1 = fmaf(p0.y, en, 1.0f);
                        float f2 = fmaf(p0.z, en, 1.0f);
                        float f3 = fmaf(p0.w, en, 1.0f);
                        float f4 = fmaf(p1.x, en, 1.0f);
                        float f5 = fmaf(p1.y, en, 1.0f);
                        float f6 = fmaf(p1.z, en, 1.0f);
                        float f7 = fmaf(p1.w, en, 1.0f);
                        cnt += (f0 > TH) ? 1.0f : 0.0f;
                        cnt += (f1 > TH) ? 1.0f : 0.0f;
                        cnt += (f2 > TH) ? 1.0f : 0.0f;
                        cnt += (f3 > TH) ? 1.0f : 0.0f;
                        cnt += (f4 > TH) ? 1.0f : 0.0f;
                        cnt += (f5 > TH) ? 1.0f : 0.0f;
                        cnt += (f6 > TH) ? 1.0f : 0.0f;
                        cnt += (f7 > TH) ? 1.0f : 0.0f;
                        float pa = ((f0 > TH) ? f0 : 1.0f);
                        pa *= ((f1 > TH) ? f1 : 1.0f);
                        pa *= ((f2 > TH) ? f2 : 1.0f);
                        pa *= ((f3 > TH) ? f3 : 1.0f);
                        float pb = ((f4 > TH) ? f4 : 1.0f);
                        pb *= ((f5 > TH) ? f5 : 1.0f);
                        pb *= ((f6 > TH) ? f6 : 1.0f);
                        pb *= ((f7 > TH) ? f7 : 1.0f);
                        trip += LN2 * (fast_log2(pa) + fast_log2(pb));
                    }
                }
            }
            cnt  += __shfl_xor_sync(0xffffffffu, cnt, 1);
            cnt  += __shfl_xor_sync(0xffffffffu, cnt, 2);
            trip += __shfl_xor_sync(0xffffffffu, trip, 1);
            trip += __shfl_xor_sync(0xffffffffu, trip, 2);
            neg  += __shfl_xor_sync(0xffffffffu, neg, 1);
            neg  += __shfl_xor_sync(0xffffffffu, neg, 2);
            if ((lane & 3) == 0) {
                atomicAdd(&g_row[gi * 4 + 0], cnt);
                atomicAdd(&g_row[gi * 4 + 1], trip);
                atomicAdd(&g_row[gi * 4 + 3], neg);
            }
        }
    }

    // ---- last-block finalize ----
    __syncthreads();
    __shared__ int slast;
    if (tid == 0) {
        __threadfence();
        int o = atomicAdd(&g_done, 1);
        slast = (o == (int)(gridDim.x * gridDim.y) - 1);
    }
    __syncthreads();
    if (!slast) return;
    __threadfence();

    double sm = 0, tc = 0, acd = 0, psd = 0, nsd = 0;
    for (int i = tid; i < NN; i += 256) {
        float4 r = *reinterpret_cast<const float4*>(g_row + i * 4);
        tc += (double)r.x; psd += (double)r.z; nsd += (double)r.w;
        if (r.x > 0.0f) sm += (double)(r.y / r.x);
        else            acd += 1.0;
    }
    #pragma unroll
    for (int o = 16; o; o >>= 1) {
        sm  += __shfl_xor_sync(0xffffffffu, sm, o);
        tc  += __shfl_xor_sync(0xffffffffu, tc, o);
        acd += __shfl_xor_sync(0xffffffffu, acd, o);
        psd += __shfl_xor_sync(0xffffffffu, psd, o);
        nsd += __shfl_xor_sync(0xffffffffu, nsd, o);
    }
    __shared__ double sh[5][8];
    int w = tid >> 5;
    if ((tid & 31) == 0) { sh[0][w] = sm; sh[1][w] = tc; sh[2][w] = acd; sh[3][w] = psd; sh[4][w] = nsd; }
    __syncthreads();
    if (tid == 0) {
        double Sm = 0, Tc = 0, Ac = 0, Ps = 0, Ns = 0;
        #pragma unroll
        for (int ww = 0; ww < 8; ww++) {
            Sm += sh[0][ww]; Tc += sh[1][ww]; Ac += sh[2][ww]; Ps += sh[3][ww]; Ns += sh[4][ww];
        }
        float loss = (Tc > 0.0) ? (float)(Sm / Tc) : 0.0f;
        if (out_size >= 1) out[0] = loss;
        if (out_size >= 2) out[1] = (float)(Ac / (double)NN);
        if (out_size >= 3) out[2] = (float)(Ps / ((double)NN * (KPC - 1)));
        if (out_size >= 4) out[3] = (float)(Ns / ((double)NN * (NN - KPC)));
    }
    for (int idx = 4 + tid; idx < out_size; idx += 256) out[idx] = 0.0f;
}

// ---------------------------------------------------------------------------
extern "C" void kernel_launch(void* const* d_in, const int* in_sizes, int n_in,
                              void* d_out, int out_size) {
    const float* inputs = (const float*)d_in[0];
    (void)in_sizes; (void)n_in;
    float* out = (float*)d_out;

    cudaFuncSetAttribute(fused_kernel, cudaFuncAttributeMaxDynamicSharedMemorySize, SMEM_TOTAL);

    normalize_kernel<<<NN, 128>>>(inputs);
    posprep_kernel<<<NN / KPC, 64>>>();
    fused_kernel<<<dim3(NN / TN, NN / TM), 256, SMEM_TOTAL>>>(out, out_size);
}

// round 6
// speedup vs baseline: 2.6862x; 1.3283x over previous
#include <cuda_runtime.h>
#include <cuda_fp16.h>
#include <cstdint>

#define NN 2048
#define DD 512
#define KPC 8
#define TM 128
#define TN 128
#define KS 64
#define NSLAB (DD / KS)

// ---------------- scratch (no allocations allowed) ----------------
__device__ __half g_xf[NN * DD];             // fp16 normalized (MMA operand)
__device__ float g_sq[NN];
__device__ float g_pos[NN * 8];              // P_k = exp(pos dist), self slot = 0
__device__ float g_row[NN * 4];              // cnt, trip_sum, pos_sum, neg_sum
__device__ int g_done;

// ---------------- helpers ----------------
__device__ __forceinline__ uint32_t smem_to_u32(const void* p) {
    uint32_t a;
    asm("{ .reg .u64 t; cvta.to.shared.u64 t, %1; cvt.u32.u64 %0, t; }" : "=r"(a) : "l"(p));
    return a;
}
__device__ __forceinline__ float fast_exp2(float x) { float y; asm("ex2.approx.f32 %0, %1;" : "=f"(y) : "f"(x)); return y; }
__device__ __forceinline__ float fast_log2(float x) { float y; asm("lg2.approx.f32 %0, %1;" : "=f"(y) : "f"(x)); return y; }
__device__ __forceinline__ float warp_sum(float v) {
    #pragma unroll
    for (int o = 16; o; o >>= 1) v += __shfl_xor_sync(0xffffffffu, v, o);
    return v;
}

#define CPA(dst, src) \
    asm volatile("cp.async.cg.shared.global [%0], [%1], 16;" :: "r"(dst), "l"(src))
#define CPA_COMMIT() asm volatile("cp.async.commit_group;" ::: "memory")

__device__ __forceinline__ void ldm_x4(uint32_t* r, uint32_t addr) {
    asm volatile("ldmatrix.sync.aligned.m8n8.x4.shared.b16 {%0,%1,%2,%3}, [%4];"
                 : "=r"(r[0]), "=r"(r[1]), "=r"(r[2]), "=r"(r[3]) : "r"(addr));
}
__device__ __forceinline__ void mma_fp16(float* c, const uint32_t* a, uint32_t b0, uint32_t b1) {
    asm volatile(
        "mma.sync.aligned.m16n8k16.row.col.f32.f16.f16.f32 "
        "{%0,%1,%2,%3}, {%4,%5,%6,%7}, {%8,%9}, {%0,%1,%2,%3};"
        : "+f"(c[0]), "+f"(c[1]), "+f"(c[2]), "+f"(c[3])
        : "r"(a[0]), "r"(a[1]), "r"(a[2]), "r"(a[3]), "r"(b0), "r"(b1));
}

// ---------------------------------------------------------------------------
// 1) prep: per-class (8 rows): normalize (fp32 in smem), write fp16 + sq,
//    8x8 intra-class dists -> P=exp(p) (self=0), init g_row. One launch.
// ---------------------------------------------------------------------------
#define XPAD 4
__global__ __launch_bounds__(256) void prep_kernel(const float* __restrict__ in) {
    __shared__ float xs[KPC][DD + XPAD];
    __shared__ float ssq[KPC];
    const int cls = blockIdx.x;
    const int tid = threadIdx.x;
    const int w = tid >> 5;          // warp = row within class
    const int l = tid & 31;
    const int row = cls * KPC + w;
    if (cls == 0 && tid == 0) g_done = 0;

    // each lane: 16 floats (4 float4)
    float4 v[4];
    const float4* src = reinterpret_cast<const float4*>(in + row * DD) + l * 4;
    #pragma unroll
    for (int q = 0; q < 4; q++) v[q] = src[q];
    float ss = 0.0f;
    #pragma unroll
    for (int q = 0; q < 4; q++)
        ss += v[q].x * v[q].x + v[q].y * v[q].y + v[q].z * v[q].z + v[q].w * v[q].w;
    ss = warp_sum(ss);
    float s = 4.0f * rsqrtf(ss);

    __half2* pf = reinterpret_cast<__half2*>(g_xf + row * DD + l * 16);
    #pragma unroll
    for (int q = 0; q < 4; q++) {
        float4 o4 = make_float4(v[q].x * s, v[q].y * s, v[q].z * s, v[q].w * s);
        xs[w][l * 16 + q * 4 + 0] = o4.x;
        xs[w][l * 16 + q * 4 + 1] = o4.y;
        xs[w][l * 16 + q * 4 + 2] = o4.z;
        xs[w][l * 16 + q * 4 + 3] = o4.w;
        pf[q * 2 + 0] = __half2(__float2half_rn(o4.x), __float2half_rn(o4.y));
        pf[q * 2 + 1] = __half2(__float2half_rn(o4.z), __float2half_rn(o4.w));
    }
    if (l == 0) { g_sq[row] = ss * s * s; ssq[w] = ss * s * s; }
    __syncthreads();

    if (tid < 64) {
        const float L2E = 1.4426950408889634f;
        int a = tid >> 3, b = tid & 7;
        float dot = 0.0f;
        #pragma unroll 4
        for (int q = 0; q < DD; q += 4) {
            dot += xs[a][q + 0] * xs[b][q + 0] + xs[a][q + 1] * xs[b][q + 1]
                 + xs[a][q + 2] * xs[b][q + 2] + xs[a][q + 3] * xs[b][q + 3];
        }
        int ia = cls * KPC + a;
        float p = ssq[a] + ssq[b] - 2.0f * dot;
        bool self = (a == b);
        g_pos[ia * 8 + b] = self ? 0.0f : fast_exp2(p * L2E);
        float ps = self ? 0.0f : p;
        ps += __shfl_xor_sync(0xffffffffu, ps, 1);
        ps += __shfl_xor_sync(0xffffffffu, ps, 2);
        ps += __shfl_xor_sync(0xffffffffu, ps, 4);
        if (b == 0) {
            g_row[ia * 4 + 0] = 0.0f;
            g_row[ia * 4 + 1] = 0.0f;
            g_row[ia * 4 + 2] = ps;
            g_row[ia * 4 + 3] = 0.0f;
        }
    }
}

// ---------------------------------------------------------------------------
// 2) fused HMMA(fp16) Gram + triplet epilogue + last-block finalize
//    tile 128x128, 2 CTAs/SM for MMA/epilogue overlap
// ---------------------------------------------------------------------------
#define SM_SQI 0
#define SM_SQJ 512
#define SM_PI  1024
#define SM_BUF 6144
#define A_OFF 0
#define B_OFF 16384
#define BUFSZ 32768
#define SMEM_TOTAL (SM_BUF + 2 * BUFSZ)

__device__ __forceinline__ void load_slab_async(uint32_t smb, int buf, int s,
                                                int bi, int bj, int tid) {
    const int k0 = s * KS;
    const uint32_t bufb = smb + SM_BUF + buf * BUFSZ;
    const int row = tid >> 1;
    const int cb = (tid & 1) * 4;
    // A: 128 rows x 8 chunks of 16B; 2 threads per row
    {
        const char* sp = reinterpret_cast<const char*>(g_xf + (bi + row) * DD + k0);
        uint32_t dA = bufb + A_OFF + row * 128;
        #pragma unroll
        for (int c = 0; c < 4; c++) {
            int ch = cb + c;
            CPA(dA + (((ch ^ (row & 7))) << 4), sp + ch * 16);
        }
    }
    // B: 128 rows x 8 chunks; 2 threads per row
    {
        const char* sp = reinterpret_cast<const char*>(g_xf + (bj + row) * DD + k0);
        uint32_t dB = bufb + B_OFF + row * 128;
        #pragma unroll
        for (int c = 0; c < 4; c++) {
            int ch = cb + c;
            CPA(dB + (((ch ^ (row & 7))) << 4), sp + ch * 16);
        }
    }
}

__global__ __launch_bounds__(256, 2) void fused_kernel(float* __restrict__ out, int out_size) {
    extern __shared__ char smem[];
    const int tid = threadIdx.x;
    const int wid = tid >> 5;
    const int lane = tid & 31;
    const int bi = blockIdx.y * TM;
    const int bj = blockIdx.x * TN;
    const int mloc = (wid >> 2) * 64;    // 2 m-warps
    const int nloc = (wid & 3) * 32;     // 4 n-warps
    const uint32_t smb = smem_to_u32(smem);
    float* sSqi = reinterpret_cast<float*>(smem + SM_SQI);
    float* sSqj = reinterpret_cast<float*>(smem + SM_SQJ);
    float* sPi  = reinterpret_cast<float*>(smem + SM_PI);

    load_slab_async(smb, 0, 0, bi, bj, tid);
    CPA_COMMIT();

    if (tid < 128) sSqi[tid] = g_sq[bi + tid];
    else           sSqj[tid - 128] = g_sq[bj + (tid - 128)];
    reinterpret_cast<float4*>(sPi)[tid] = reinterpret_cast<const float4*>(g_pos + bi * 8)[tid];

    float acc[4][4][4];
    #pragma unroll
    for (int mi = 0; mi < 4; mi++)
        #pragma unroll
        for (int ni = 0; ni < 4; ni++)
            #pragma unroll
            for (int r = 0; r < 4; r++) acc[mi][ni][r] = 0.0f;

    const int rA = (lane & 7) + (((lane >> 3) & 1) << 3);
    const int cSel = lane >> 4;
    const int x7 = lane & 7;

    #pragma unroll 1
    for (int s = 0; s < NSLAB; s++) {
        const int b = s & 1;
        if (s + 1 < NSLAB) { load_slab_async(smb, 1 - b, s + 1, bi, bj, tid); CPA_COMMIT(); }
        if (s + 1 < NSLAB) asm volatile("cp.async.wait_group 1;" ::: "memory");
        else               asm volatile("cp.async.wait_group 0;" ::: "memory");
        __syncthreads();

        const uint32_t base = smb + SM_BUF + b * BUFSZ;
        #pragma unroll
        for (int ks = 0; ks < 4; ks++) {
            uint32_t af[4][4];
            #pragma unroll
            for (int mi = 0; mi < 4; mi++) {
                int row = mloc + mi * 16 + rA;
                uint32_t ad = base + A_OFF + row * 128 + ((((2 * ks + cSel) ^ x7)) << 4);
                ldm_x4(af[mi], ad);
            }
            uint32_t bfr[2][4];
            #pragma unroll
            for (int nt = 0; nt < 2; nt++) {
                int row = nloc + nt * 16 + rA;
                uint32_t bd = base + B_OFF + row * 128 + ((((2 * ks + cSel) ^ x7)) << 4);
                ldm_x4(bfr[nt], bd);
            }
            #pragma unroll
            for (int mi = 0; mi < 4; mi++)
                #pragma unroll
                for (int nt = 0; nt < 2; nt++) {
                    mma_fp16(acc[mi][2 * nt],     af[mi], bfr[nt][0], bfr[nt][2]);
                    mma_fp16(acc[mi][2 * nt + 1], af[mi], bfr[nt][1], bfr[nt][3]);
                }
        }
        __syncthreads();
    }

    // ---- triplet epilogue on register accumulators ----
    const float L2E = 1.4426950408889634f;
    const float LN2 = 0.6931471805599453f;
    const float TH  = 1.99970566f;            // 1 + (exp(0.693f)-1)

    #pragma unroll
    for (int mi = 0; mi < 4; mi++) {
        #pragma unroll
        for (int h = 0; h < 2; h++) {
            const int rl = mloc + mi * 16 + h * 8 + (lane >> 2);
            const int gi = bi + rl;
            const float sqi = sSqi[rl];
            const float4 p0 = *reinterpret_cast<const float4*>(sPi + rl * 8);
            const float4 p1 = *reinterpret_cast<const float4*>(sPi + rl * 8 + 4);
            float cnt = 0.0f, trip = 0.0f, neg = 0.0f;
            #pragma unroll
            for (int ni = 0; ni < 4; ni++) {
                #pragma unroll
                for (int rr = 0; rr < 2; rr++) {
                    const int cl = nloc + ni * 8 + (lane & 3) * 2 + rr;
                    const float d = sqi + sSqj[cl] - 2.0f * acc[mi][ni][h * 2 + rr];
                    const int gj = bj + cl;
                    if ((gi >> 3) != (gj >> 3)) {
                        neg += d;
                        float en = fast_exp2(-d * L2E);
                        float f0 = fmaf(p0.x, en, 1.0f);
                        float f1 = fmaf(p0.y, en, 1.0f);
                        float f2 = fmaf(p0.z, en, 1.0f);
                        float f3 = fmaf(p0.w, en, 1.0f);
                        float f4 = fmaf(p1.x, en, 1.0f);
                        float f5 = fmaf(p1.y, en, 1.0f);
                        float f6 = fmaf(p1.z, en, 1.0f);
                        float f7 = fmaf(p1.w, en, 1.0f);
                        cnt += (f0 > TH) ? 1.0f : 0.0f;
                        cnt += (f1 > TH) ? 1.0f : 0.0f;
                        cnt += (f2 > TH) ? 1.0f : 0.0f;
                        cnt += (f3 > TH) ? 1.0f : 0.0f;
                        cnt += (f4 > TH) ? 1.0f : 0.0f;
                        cnt += (f5 > TH) ? 1.0f : 0.0f;
                        cnt += (f6 > TH) ? 1.0f : 0.0f;
                        cnt += (f7 > TH) ? 1.0f : 0.0f;
                        float pa = ((f0 > TH) ? f0 : 1.0f);
                        pa *= ((f1 > TH) ? f1 : 1.0f);
                        pa *= ((f2 > TH) ? f2 : 1.0f);
                        pa *= ((f3 > TH) ? f3 : 1.0f);
                        float pb = ((f4 > TH) ? f4 : 1.0f);
                        pb *= ((f5 > TH) ? f5 : 1.0f);
                        pb *= ((f6 > TH) ? f6 : 1.0f);
                        pb *= ((f7 > TH) ? f7 : 1.0f);
                        trip += LN2 * (fast_log2(pa) + fast_log2(pb));
                    }
                }
            }
            cnt  += __shfl_xor_sync(0xffffffffu, cnt, 1);
            cnt  += __shfl_xor_sync(0xffffffffu, cnt, 2);
            trip += __shfl_xor_sync(0xffffffffu, trip, 1);
            trip += __shfl_xor_sync(0xffffffffu, trip, 2);
            neg  += __shfl_xor_sync(0xffffffffu, neg, 1);
            neg  += __shfl_xor_sync(0xffffffffu, neg, 2);
            if ((lane & 3) == 0) {
                atomicAdd(&g_row[gi * 4 + 0], cnt);
                atomicAdd(&g_row[gi * 4 + 1], trip);
                atomicAdd(&g_row[gi * 4 + 3], neg);
            }
        }
    }

    // ---- last-block finalize ----
    __syncthreads();
    __shared__ int slast;
    if (tid == 0) {
        __threadfence();
        int o = atomicAdd(&g_done, 1);
        slast = (o == (int)(gridDim.x * gridDim.y) - 1);
    }
    __syncthreads();
    if (!slast) return;
    __threadfence();

    double sm = 0, tc = 0, acd = 0, psd = 0, nsd = 0;
    for (int i = tid; i < NN; i += 256) {
        float4 r = *reinterpret_cast<const float4*>(g_row + i * 4);
        tc += (double)r.x; psd += (double)r.z; nsd += (double)r.w;
        if (r.x > 0.0f) sm += (double)(r.y / r.x);
        else            acd += 1.0;
    }
    #pragma unroll
    for (int o = 16; o; o >>= 1) {
        sm  += __shfl_xor_sync(0xffffffffu, sm, o);
        tc  += __shfl_xor_sync(0xffffffffu, tc, o);
        acd += __shfl_xor_sync(0xffffffffu, acd, o);
        psd += __shfl_xor_sync(0xffffffffu, psd, o);
        nsd += __shfl_xor_sync(0xffffffffu, nsd, o);
    }
    __shared__ double sh[5][8];
    int w = tid >> 5;
    if ((tid & 31) == 0) { sh[0][w] = sm; sh[1][w] = tc; sh[2][w] = acd; sh[3][w] = psd; sh[4][w] = nsd; }
    __syncthreads();
    if (tid == 0) {
        double Sm = 0, Tc = 0, Ac = 0, Ps = 0, Ns = 0;
        #pragma unroll
        for (int ww = 0; ww < 8; ww++) {
            Sm += sh[0][ww]; Tc += sh[1][ww]; Ac += sh[2][ww]; Ps += sh[3][ww]; Ns += sh[4][ww];
        }
        float loss = (Tc > 0.0) ? (float)(Sm / Tc) : 0.0f;
        if (out_size >= 1) out[0] = loss;
        if (out_size >= 2) out[1] = (float)(Ac / (double)NN);
        if (out_size >= 3) out[2] = (float)(Ps / ((double)NN * (KPC - 1)));
        if (out_size >= 4) out[3] = (float)(Ns / ((double)NN * (NN - KPC)));
    }
    for (int idx = 4 + tid; idx < out_size; idx += 256) out[idx] = 0.0f;
}

// ---------------------------------------------------------------------------
extern "C" void kernel_launch(void* const* d_in, const int* in_sizes, int n_in,
                              void* d_out, int out_size) {
    const float* inputs = (const float*)d_in[0];
    (void)in_sizes; (void)n_in;
    float* out = (float*)d_out;

    cudaFuncSetAttribute(fused_kernel, cudaFuncAttributeMaxDynamicSharedMemorySize, SMEM_TOTAL);

    prep_kernel<<<NN / KPC, 256>>>(inputs);
    fused_kernel<<<dim3(NN / TN, NN / TM), 256, SMEM_TOTAL>>>(out, out_size);
}